// round 12
// baseline (speedup 1.0000x reference)
#include <cuda_runtime.h>
#include <cstdint>

#define BB 2
#define CC 32
#define DD 64
#define HH 128
#define WW 128
#define NBC (BB*CC)
#define SLICE (HH*WW)
#define NCTA 512             // 64 bc x 8 hblocks(16 rows), full 64-slice walk
#define NWARP 4

// Per-CTA partials: crown, root, sx, sy (float4) + sz (float). Fully rewritten.
__device__ float4 g_a[NCTA];
__device__ float  g_b[NCTA];
__device__ unsigned int g_count;   // zero at load; last CTA resets to 0

// ---- packed f32x2 helpers ----
__device__ __forceinline__ void unpack2(unsigned long long v, float& lo, float& hi) {
    asm("mov.b64 {%0,%1}, %2;" : "=f"(lo), "=f"(hi) : "l"(v));
}
__device__ __forceinline__ void acc2(unsigned long long& acc, unsigned long long v) {
    asm("add.rn.f32x2 %0, %0, %1;" : "+l"(acc) : "l"(v));
}
// acc += |b - a| elementwise (packed)
__device__ __forceinline__ void absdiff_acc2(unsigned long long& acc,
                                             unsigned long long a,
                                             unsigned long long b,
                                             unsigned long long neg1) {
    unsigned long long d;
    asm("fma.rn.f32x2 %0, %1, %2, %3;" : "=l"(d) : "l"(a), "l"(neg1), "l"(b)); // b - a
    asm("and.b64 %0, %0, 0x7FFFFFFF7FFFFFFF;" : "+l"(d));
    asm("add.rn.f32x2 %0, %0, %1;" : "+l"(acc) : "l"(d));
}
__device__ __forceinline__ float hadd2(unsigned long long v) {
    float a, b; unpack2(v, a, b); return a + b;
}

__device__ __forceinline__ ulonglong2 ldrow(const float* base, int roff, int lane) {
    return reinterpret_cast<const ulonglong2*>(base + roff)[lane];
}

// x-diffs for one row held as (r.x=x0x1, r.y=x2x3)
__device__ __forceinline__ float xdiff_row(const ulonglong2& r, int lane) {
    float x0, x1, x2, x3;
    unpack2(r.x, x0, x1);
    unpack2(r.y, x2, x3);
    const float nlx = __shfl_down_sync(0xffffffffu, x0, 1);
    float s = fabsf(x1 - x0) + fabsf(x2 - x1) + fabsf(x3 - x2);
    if (lane < 31) s += fabsf(nlx - x3);
    return s;
}

// One slice-step for a warp's 4 carried rows. do_z: prefetch next slice + z-diff.
__device__ __forceinline__ void step(const float* p, int lane, bool has_y, bool do_z,
                                     ulonglong2 c[4],
                                     unsigned long long& accS,
                                     unsigned long long& accY,
                                     unsigned long long& accZ,
                                     float& sx,
                                     unsigned long long neg1) {
    ulonglong2 n[4];
    if (do_z) {
        #pragma unroll
        for (int r = 0; r < 4; r++) n[r] = ldrow(p, SLICE + r * WW, lane);
    }
    ulonglong2 yn;
    if (has_y) yn = ldrow(p, 4 * WW, lane);

    #pragma unroll
    for (int r = 0; r < 4; r++) {
        acc2(accS, c[r].x); acc2(accS, c[r].y);
        sx += xdiff_row(c[r], lane);
    }
    #pragma unroll
    for (int r = 0; r < 3; r++) {
        absdiff_acc2(accY, c[r].x, c[r + 1].x, neg1);
        absdiff_acc2(accY, c[r].y, c[r + 1].y, neg1);
    }
    if (has_y) {
        absdiff_acc2(accY, c[3].x, yn.x, neg1);
        absdiff_acc2(accY, c[3].y, yn.y, neg1);
    }
    if (do_z) {
        #pragma unroll
        for (int r = 0; r < 4; r++) {
            absdiff_acc2(accZ, c[r].x, n[r].x, neg1);
            absdiff_acc2(accZ, c[r].y, n[r].y, neg1);
            c[r] = n[r];
        }
    }
}

// CTA = (bc, 16-row block). 4 warps; warp w carries rows h0..h0+3 (h0=hb*16+4w)
// across ALL 64 z-slices (no z-seam re-read). Crown/root split = two 32-iter
// loops with different sum accumulators; the d=31->32 z-diff happens in the
// first loop's last prefetch. 3 of 4 y-diffs are register-register; the seam
// y-diff (row h0+4) is the next warp's current row -> L1-coalesced.
__global__ void __launch_bounds__(128) fused_kernel(const float* __restrict__ seg,
                                                    float* __restrict__ out) {
    __shared__ float shf[5][NWARP];
    __shared__ double shd[4][NWARP];
    __shared__ bool s_last;

    const int cta  = blockIdx.x;
    const int bc   = cta >> 3;
    const int hb   = cta & 7;            // 0..7 (16-row blocks)
    const int tid  = threadIdx.x;
    const int warp = tid >> 5;
    const int lane = tid & 31;
    const int h0   = hb * 16 + warp * 4;
    const bool has_y = (h0 + 4 < HH);    // false only for rows 124..127
    const unsigned long long neg1 = 0xBF800000BF800000ULL;

    const float* p = seg + (size_t)bc * DD * SLICE + h0 * WW;

    unsigned long long acc_c = 0ULL, acc_r = 0ULL, acc_y = 0ULL, acc_z = 0ULL;
    float sx = 0.f;

    ulonglong2 c[4];
    #pragma unroll
    for (int r = 0; r < 4; r++) c[r] = ldrow(p, r * WW, lane);

    // crown half: d = 0..31 (every iteration prefetches d+1 and does z-diff)
    #pragma unroll 1
    for (int d = 0; d < 32; d++) {
        step(p, lane, has_y, true, c, acc_c, acc_y, acc_z, sx, neg1);
        p += SLICE;
    }
    // root half: d = 32..62
    #pragma unroll 1
    for (int d = 32; d < 63; d++) {
        step(p, lane, has_y, true, c, acc_r, acc_y, acc_z, sx, neg1);
        p += SLICE;
    }
    // epilogue: d = 63, no next slice
    step(p, lane, has_y, false, c, acc_r, acc_y, acc_z, sx, neg1);

    float crown = hadd2(acc_c);
    float root  = hadd2(acc_r);
    float sy    = hadd2(acc_y);
    float sz    = hadd2(acc_z);

    #pragma unroll
    for (int off = 16; off > 0; off >>= 1) {
        crown += __shfl_xor_sync(0xffffffffu, crown, off);
        root  += __shfl_xor_sync(0xffffffffu, root,  off);
        sx    += __shfl_xor_sync(0xffffffffu, sx,    off);
        sy    += __shfl_xor_sync(0xffffffffu, sy,    off);
        sz    += __shfl_xor_sync(0xffffffffu, sz,    off);
    }

    if (lane == 0) {
        shf[0][warp] = crown; shf[1][warp] = root;
        shf[2][warp] = sx;    shf[3][warp] = sy; shf[4][warp] = sz;
    }
    __syncthreads();

    if (tid == 0) {
        float t0 = 0.f, t1 = 0.f, t2 = 0.f, t3 = 0.f, t4 = 0.f;
        #pragma unroll
        for (int w = 0; w < NWARP; w++) {
            t0 += shf[0][w]; t1 += shf[1][w]; t2 += shf[2][w];
            t3 += shf[3][w]; t4 += shf[4][w];
        }
        g_a[cta] = make_float4(t0, t1, t2, t3);
        g_b[cta] = t4;
        __threadfence();
        const unsigned old = atomicAdd(&g_count, 1u);
        s_last = (old == NCTA - 1);
    }
    __syncthreads();
    if (!s_last) return;

    // ---- finalize in the last CTA (128 threads; tids 0..63 own a bc) ----
    __threadfence();

    double loss = 0.0, tx = 0.0, ty = 0.0, tz = 0.0;
    if (tid < NBC) {
        double crn = 0.0, rt = 0.0;
        #pragma unroll
        for (int k = 0; k < 8; k++) {          // 8 hblocks
            const float4 a = g_a[tid * 8 + k];
            const float  b = g_b[tid * 8 + k];
            crn += (double)a.x; rt += (double)a.y;
            tx  += (double)a.z; ty += (double)a.w; tz += (double)b;
        }
        if ((crn + rt) > 0.0 && rt > 0.0) {
            const double r = crn / rt - 1.2;
            loss = r * r;
        }
    }

    #pragma unroll
    for (int off = 16; off > 0; off >>= 1) {
        loss += __shfl_xor_sync(0xffffffffu, loss, off);
        tx   += __shfl_xor_sync(0xffffffffu, tx,   off);
        ty   += __shfl_xor_sync(0xffffffffu, ty,   off);
        tz   += __shfl_xor_sync(0xffffffffu, tz,   off);
    }

    if (lane == 0) { shd[0][warp] = loss; shd[1][warp] = tx; shd[2][warp] = ty; shd[3][warp] = tz; }
    __syncthreads();

    if (tid == 0) {
        double L = 0.0, Tx = 0.0, Ty = 0.0, Tz = 0.0;
        #pragma unroll
        for (int w = 0; w < NWARP; w++) {
            L += shd[0][w]; Tx += shd[1][w]; Ty += shd[2][w]; Tz += shd[3][w];
        }
        const double cr_loss = L / (double)NBC;
        const double Nx = (double)BB * CC * DD * HH * (WW - 1);
        const double Ny = (double)BB * CC * DD * (HH - 1) * WW;
        const double Nz = (double)BB * CC * (DD - 1) * HH * WW;
        const double tv = Tx / Nx + Ty / Ny + Tz / Nz;

        const double crown_root = cr_loss * 2.0;   // CROWN_ROOT_W
        const double smooth     = tv * 1.5;        // SMOOTH_W
        out[0] = (float)crown_root;
        out[1] = (float)smooth;
        out[2] = (float)(crown_root + smooth);

        g_count = 0;   // reset for next graph replay
    }
}

extern "C" void kernel_launch(void* const* d_in, const int* in_sizes, int n_in,
                              void* d_out, int out_size) {
    const float* seg = (const float*)d_in[0];
    float* out = (float*)d_out;
    fused_kernel<<<NCTA, 128>>>(seg, out);
}

// round 13
// speedup vs baseline: 1.2594x; 1.2594x over previous
#include <cuda_runtime.h>

#define BB 2
#define CC 32
#define DD 64
#define HH 128
#define WW 128
#define NBC (BB*CC)
#define SLICE (HH*WW)
#define NCTA 512             // 64 bc x 4 hblocks(32 rows) x 2 zhalves

// Per-CTA partials [sum, sx, sy, sz]; fully rewritten each run.
__device__ float4 g_part[NCTA];
__device__ unsigned int g_count;   // zero at load; last CTA resets to 0

// ---- packed f32x2 helpers ----
__device__ __forceinline__ void unpack2(unsigned long long v, float& lo, float& hi) {
    asm("mov.b64 {%0,%1}, %2;" : "=f"(lo), "=f"(hi) : "l"(v));
}
__device__ __forceinline__ void acc2(unsigned long long& acc, unsigned long long v) {
    asm("add.rn.f32x2 %0, %0, %1;" : "+l"(acc) : "l"(v));
}
// acc += |b - a| elementwise (packed)
__device__ __forceinline__ void absdiff_acc2(unsigned long long& acc,
                                             unsigned long long a,
                                             unsigned long long b,
                                             unsigned long long neg1) {
    unsigned long long d;
    asm("fma.rn.f32x2 %0, %1, %2, %3;" : "=l"(d) : "l"(a), "l"(neg1), "l"(b)); // b - a
    asm("and.b64 %0, %0, 0x7FFFFFFF7FFFFFFF;" : "+l"(d));
    asm("add.rn.f32x2 %0, %0, %1;" : "+l"(acc) : "l"(d));
}
__device__ __forceinline__ float hadd2(unsigned long long v) {
    float a, b; unpack2(v, a, b); return a + b;
}

// streaming (evict-first) 16B load
__device__ __forceinline__ ulonglong2 ldcs128(const float* base, int roff, int lane) {
    ulonglong2 v;
    const float* p = base + roff + lane * 4;
    asm volatile("ld.global.cs.v2.u64 {%0, %1}, [%2];"
                 : "=l"(v.x), "=l"(v.y) : "l"(p));
    return v;
}
// default-cached 16B load (y-seam: re-read of an L1-resident line)
__device__ __forceinline__ ulonglong2 ldca128(const float* base, int roff, int lane) {
    ulonglong2 v;
    const float* p = base + roff + lane * 4;
    asm volatile("ld.global.ca.v2.u64 {%0, %1}, [%2];"
                 : "=l"(v.x), "=l"(v.y) : "l"(p));
    return v;
}

// x-diffs for one row held as (r.x=x0x1, r.y=x2x3)
__device__ __forceinline__ float xdiff_row(const ulonglong2& r, int lane) {
    float x0, x1, x2, x3;
    unpack2(r.x, x0, x1);
    unpack2(r.y, x2, x3);
    const float nlx = __shfl_down_sync(0xffffffffu, x0, 1);
    float s = fabsf(x1 - x0) + fabsf(x2 - x1) + fabsf(x3 - x2);
    if (lane < 31) s += fabsf(nlx - x3);
    return s;
}

// CTA = (bc, 32-row block, z-half). 8 warps; warp w carries 4 consecutive rows
// h0..h0+3 across 32 z-slices. 3 of 4 y-diffs are register-register; the seam
// y-diff loads row h0+4 (L1 hit). z-diff uses the prefetched next-slice quad.
// zh=0 additionally loads slice 32 once for the z seam.
__global__ void __launch_bounds__(256) fused_kernel(const float* __restrict__ seg,
                                                    float* __restrict__ out) {
    const int cta  = blockIdx.x;
    const int bc   = cta >> 3;
    const int rem  = cta & 7;
    const int hb   = rem >> 1;           // 0..3 (32-row blocks)
    const int zh   = rem & 1;
    const int warp = threadIdx.x >> 5;
    const int lane = threadIdx.x & 31;
    const int h0   = hb * 32 + warp * 4;
    const bool has_y = (h0 + 4 < HH);    // false only for rows 124..127
    const unsigned long long neg1 = 0xBF800000BF800000ULL;

    const float* p = seg + (size_t)bc * DD * SLICE + (size_t)(zh * 32) * SLICE + h0 * WW;

    unsigned long long acc_s = 0ULL, acc_y = 0ULL, acc_z = 0ULL;
    float sx = 0.f;

    ulonglong2 c[4];
    #pragma unroll
    for (int r = 0; r < 4; r++)
        c[r] = ldcs128(p, r * WW, lane);

    #pragma unroll 1
    for (int i = 0; i < 31; i++) {
        // prefetch next-slice quad (streaming) + y-seam row (cached; L1-resident)
        ulonglong2 n[4];
        #pragma unroll
        for (int r = 0; r < 4; r++)
            n[r] = ldcs128(p, SLICE + r * WW, lane);
        ulonglong2 yn;
        if (has_y) yn = ldca128(p, 4 * WW, lane);

        // slice sums + x-diffs
        #pragma unroll
        for (int r = 0; r < 4; r++) {
            acc2(acc_s, c[r].x); acc2(acc_s, c[r].y);
            sx += xdiff_row(c[r], lane);
        }
        // y: 3 in-quad diffs + seam
        #pragma unroll
        for (int r = 0; r < 3; r++) {
            absdiff_acc2(acc_y, c[r].x, c[r + 1].x, neg1);
            absdiff_acc2(acc_y, c[r].y, c[r + 1].y, neg1);
        }
        if (has_y) {
            absdiff_acc2(acc_y, c[3].x, yn.x, neg1);
            absdiff_acc2(acc_y, c[3].y, yn.y, neg1);
        }
        // z: diff vs prefetched next slice
        #pragma unroll
        for (int r = 0; r < 4; r++) {
            absdiff_acc2(acc_z, c[r].x, n[r].x, neg1);
            absdiff_acc2(acc_z, c[r].y, n[r].y, neg1);
            c[r] = n[r];
        }
        p += SLICE;
    }

    // epilogue: local slice 31 (global d = zh*32 + 31)
    {
        ulonglong2 yn;
        if (has_y) yn = ldca128(p, 4 * WW, lane);

        #pragma unroll
        for (int r = 0; r < 4; r++) {
            acc2(acc_s, c[r].x); acc2(acc_s, c[r].y);
            sx += xdiff_row(c[r], lane);
        }
        #pragma unroll
        for (int r = 0; r < 3; r++) {
            absdiff_acc2(acc_y, c[r].x, c[r + 1].x, neg1);
            absdiff_acc2(acc_y, c[r].y, c[r + 1].y, neg1);
        }
        if (has_y) {
            absdiff_acc2(acc_y, c[3].x, yn.x, neg1);
            absdiff_acc2(acc_y, c[3].y, yn.y, neg1);
        }
        if (zh == 0) {   // z seam (slice 31 vs 32) owned by left CTA
            #pragma unroll
            for (int r = 0; r < 4; r++) {
                const ulonglong2 n = ldcs128(p, SLICE + r * WW, lane);
                absdiff_acc2(acc_z, c[r].x, n.x, neg1);
                absdiff_acc2(acc_z, c[r].y, n.y, neg1);
            }
        }
    }

    float ssum = hadd2(acc_s);
    float sy   = hadd2(acc_y);
    float sz   = hadd2(acc_z);

    #pragma unroll
    for (int off = 16; off > 0; off >>= 1) {
        ssum += __shfl_xor_sync(0xffffffffu, ssum, off);
        sx   += __shfl_xor_sync(0xffffffffu, sx,   off);
        sy   += __shfl_xor_sync(0xffffffffu, sy,   off);
        sz   += __shfl_xor_sync(0xffffffffu, sz,   off);
    }

    __shared__ float sh[4][8];
    if (lane == 0) { sh[0][warp] = ssum; sh[1][warp] = sx; sh[2][warp] = sy; sh[3][warp] = sz; }
    __syncthreads();

    __shared__ bool s_last;
    if (threadIdx.x == 0) {
        float t0 = 0.f, t1 = 0.f, t2 = 0.f, t3 = 0.f;
        #pragma unroll
        for (int w = 0; w < 8; w++) {
            t0 += sh[0][w]; t1 += sh[1][w]; t2 += sh[2][w]; t3 += sh[3][w];
        }
        g_part[cta] = make_float4(t0, t1, t2, t3);
        __threadfence();
        const unsigned old = atomicAdd(&g_count, 1u);
        s_last = (old == NCTA - 1);
    }
    __syncthreads();
    if (!s_last) return;

    // ---- finalize in the last CTA ----
    __threadfence();

    const int tid = threadIdx.x;
    double loss = 0.0, tx = 0.0, ty = 0.0, tz = 0.0;
    if (tid < NBC) {
        double crn = 0.0, rt = 0.0;
        #pragma unroll
        for (int k = 0; k < 8; k++) {          // 4 hblocks x 2 zhalves
            const float4 a = g_part[tid * 8 + k];
            if ((k & 1) == 0) crn += (double)a.x;   // zh=0 -> crown (d 0..31)
            else              rt  += (double)a.x;   // zh=1 -> root  (d 32..63)
            tx += (double)a.y; ty += (double)a.z; tz += (double)a.w;
        }
        if ((crn + rt) > 0.0 && rt > 0.0) {
            const double r = crn / rt - 1.2;
            loss = r * r;
        }
    }

    #pragma unroll
    for (int off = 16; off > 0; off >>= 1) {
        loss += __shfl_xor_sync(0xffffffffu, loss, off);
        tx   += __shfl_xor_sync(0xffffffffu, tx,   off);
        ty   += __shfl_xor_sync(0xffffffffu, ty,   off);
        tz   += __shfl_xor_sync(0xffffffffu, tz,   off);
    }

    __shared__ double shd[4][8];
    if (lane == 0) { shd[0][warp] = loss; shd[1][warp] = tx; shd[2][warp] = ty; shd[3][warp] = tz; }
    __syncthreads();

    if (tid == 0) {
        double L = 0.0, Tx = 0.0, Ty = 0.0, Tz = 0.0;
        #pragma unroll
        for (int w = 0; w < 8; w++) {
            L += shd[0][w]; Tx += shd[1][w]; Ty += shd[2][w]; Tz += shd[3][w];
        }
        const double cr_loss = L / (double)NBC;
        const double Nx = (double)BB * CC * DD * HH * (WW - 1);
        const double Ny = (double)BB * CC * DD * (HH - 1) * WW;
        const double Nz = (double)BB * CC * (DD - 1) * HH * WW;
        const double tv = Tx / Nx + Ty / Ny + Tz / Nz;

        const double crown_root = cr_loss * 2.0;   // CROWN_ROOT_W
        const double smooth     = tv * 1.5;        // SMOOTH_W
        out[0] = (float)crown_root;
        out[1] = (float)smooth;
        out[2] = (float)(crown_root + smooth);

        g_count = 0;   // reset for next graph replay
    }
}

extern "C" void kernel_launch(void* const* d_in, const int* in_sizes, int n_in,
                              void* d_out, int out_size) {
    const float* seg = (const float*)d_in[0];
    float* out = (float*)d_out;
    fused_kernel<<<NCTA, 256>>>(seg, out);
}

// round 14
// speedup vs baseline: 1.3160x; 1.0449x over previous
#include <cuda_runtime.h>

#define BB 2
#define CC 32
#define DD 64
#define HH 128
#define WW 128
#define NBC (BB*CC)
#define SLICE (HH*WW)
#define NCTA 512             // 64 bc x 4 hblocks(32 rows) x 2 zhalves

// Per-CTA partials [sum, sx, sy, sz]; fully rewritten each run.
__device__ float4 g_part[NCTA];
__device__ unsigned int g_count;   // zero at load; last CTA resets to 0

// ---- packed f32x2 helpers ----
__device__ __forceinline__ void unpack2(unsigned long long v, float& lo, float& hi) {
    asm("mov.b64 {%0,%1}, %2;" : "=f"(lo), "=f"(hi) : "l"(v));
}
__device__ __forceinline__ void acc2(unsigned long long& acc, unsigned long long v) {
    asm("add.rn.f32x2 %0, %0, %1;" : "+l"(acc) : "l"(v));
}
// acc += |b - a| elementwise (packed)
__device__ __forceinline__ void absdiff_acc2(unsigned long long& acc,
                                             unsigned long long a,
                                             unsigned long long b,
                                             unsigned long long neg1) {
    unsigned long long d;
    asm("fma.rn.f32x2 %0, %1, %2, %3;" : "=l"(d) : "l"(a), "l"(neg1), "l"(b)); // b - a
    asm("and.b64 %0, %0, 0x7FFFFFFF7FFFFFFF;" : "+l"(d));
    asm("add.rn.f32x2 %0, %0, %1;" : "+l"(acc) : "l"(d));
}
__device__ __forceinline__ float hadd2(unsigned long long v) {
    float a, b; unpack2(v, a, b); return a + b;
}

// streaming (evict-first) 16B load — single-use bulk stream
__device__ __forceinline__ ulonglong2 ldcs128(const float* base, int roff, int lane) {
    ulonglong2 v;
    const float* p = base + roff + lane * 4;
    asm volatile("ld.global.cs.v2.u64 {%0, %1}, [%2];"
                 : "=l"(v.x), "=l"(v.y) : "l"(p));
    return v;
}
// default-cached 16B load — lines that a neighbor (or this CTA) re-reads
__device__ __forceinline__ ulonglong2 ldca128(const float* base, int roff, int lane) {
    ulonglong2 v;
    const float* p = base + roff + lane * 4;
    asm volatile("ld.global.ca.v2.u64 {%0, %1}, [%2];"
                 : "=l"(v.x), "=l"(v.y) : "l"(p));
    return v;
}
// last-use 16B load — dead after this read
__device__ __forceinline__ ulonglong2 ldlu128(const float* base, int roff, int lane) {
    ulonglong2 v;
    const float* p = base + roff + lane * 4;
    asm volatile("ld.global.lu.v2.u64 {%0, %1}, [%2];"
                 : "=l"(v.x), "=l"(v.y) : "l"(p));
    return v;
}

// x-diffs for one row held as (r.x=x0x1, r.y=x2x3)
__device__ __forceinline__ float xdiff_row(const ulonglong2& r, int lane) {
    float x0, x1, x2, x3;
    unpack2(r.x, x0, x1);
    unpack2(r.y, x2, x3);
    const float nlx = __shfl_down_sync(0xffffffffu, x0, 1);
    float s = fabsf(x1 - x0) + fabsf(x2 - x1) + fabsf(x3 - x2);
    if (lane < 31) s += fabsf(nlx - x3);
    return s;
}

// CTA = (bc, 32-row block, z-half). 8 warps; warp w carries 4 consecutive rows
// h0..h0+3 across 32 z-slices. 3 of 4 y-diffs are register-register; the seam
// y-diff loads row h0+4 (L1 hit). z-diff uses the prefetched next-slice quad.
// zh=0 additionally loads slice 32 once for the z seam (L2 hit: zh=1's prologue
// loaded those lines with .ca so they persist against the .cs stream).
__global__ void __launch_bounds__(256) fused_kernel(const float* __restrict__ seg,
                                                    float* __restrict__ out) {
    const int cta  = blockIdx.x;
    const int bc   = cta >> 3;
    const int rem  = cta & 7;
    const int hb   = rem >> 1;           // 0..3 (32-row blocks)
    const int zh   = rem & 1;
    const int warp = threadIdx.x >> 5;
    const int lane = threadIdx.x & 31;
    const int h0   = hb * 32 + warp * 4;
    const bool has_y = (h0 + 4 < HH);    // false only for rows 124..127
    const unsigned long long neg1 = 0xBF800000BF800000ULL;

    const float* p = seg + (size_t)bc * DD * SLICE + (size_t)(zh * 32) * SLICE + h0 * WW;

    unsigned long long acc_s = 0ULL, acc_y = 0ULL, acc_z = 0ULL;
    float sx = 0.f;

    // Prologue quad: zh=1's first slice (d=32) is re-read by the zh=0 neighbor's
    // z-seam -> keep cacheable (.ca). zh=0's first slice is single-use but tiny.
    ulonglong2 c[4];
    #pragma unroll
    for (int r = 0; r < 4; r++)
        c[r] = ldca128(p, r * WW, lane);

    #pragma unroll 1
    for (int i = 0; i < 31; i++) {
        // prefetch next-slice quad (streaming) + y-seam row (cached; L1-resident)
        ulonglong2 n[4];
        #pragma unroll
        for (int r = 0; r < 4; r++)
            n[r] = ldcs128(p, SLICE + r * WW, lane);
        ulonglong2 yn;
        if (has_y) yn = ldca128(p, 4 * WW, lane);

        // slice sums + x-diffs
        #pragma unroll
        for (int r = 0; r < 4; r++) {
            acc2(acc_s, c[r].x); acc2(acc_s, c[r].y);
            sx += xdiff_row(c[r], lane);
        }
        // y: 3 in-quad diffs + seam
        #pragma unroll
        for (int r = 0; r < 3; r++) {
            absdiff_acc2(acc_y, c[r].x, c[r + 1].x, neg1);
            absdiff_acc2(acc_y, c[r].y, c[r + 1].y, neg1);
        }
        if (has_y) {
            absdiff_acc2(acc_y, c[3].x, yn.x, neg1);
            absdiff_acc2(acc_y, c[3].y, yn.y, neg1);
        }
        // z: diff vs prefetched next slice
        #pragma unroll
        for (int r = 0; r < 4; r++) {
            absdiff_acc2(acc_z, c[r].x, n[r].x, neg1);
            absdiff_acc2(acc_z, c[r].y, n[r].y, neg1);
            c[r] = n[r];
        }
        p += SLICE;
    }

    // epilogue: local slice 31 (global d = zh*32 + 31)
    {
        ulonglong2 yn;
        if (has_y) yn = ldca128(p, 4 * WW, lane);

        #pragma unroll
        for (int r = 0; r < 4; r++) {
            acc2(acc_s, c[r].x); acc2(acc_s, c[r].y);
            sx += xdiff_row(c[r], lane);
        }
        #pragma unroll
        for (int r = 0; r < 3; r++) {
            absdiff_acc2(acc_y, c[r].x, c[r + 1].x, neg1);
            absdiff_acc2(acc_y, c[r].y, c[r + 1].y, neg1);
        }
        if (has_y) {
            absdiff_acc2(acc_y, c[3].x, yn.x, neg1);
            absdiff_acc2(acc_y, c[3].y, yn.y, neg1);
        }
        if (zh == 0) {   // z seam (slice 31 vs 32) owned by left CTA; dead after use
            #pragma unroll
            for (int r = 0; r < 4; r++) {
                const ulonglong2 n = ldlu128(p, SLICE + r * WW, lane);
                absdiff_acc2(acc_z, c[r].x, n.x, neg1);
                absdiff_acc2(acc_z, c[r].y, n.y, neg1);
            }
        }
    }

    float ssum = hadd2(acc_s);
    float sy   = hadd2(acc_y);
    float sz   = hadd2(acc_z);

    #pragma unroll
    for (int off = 16; off > 0; off >>= 1) {
        ssum += __shfl_xor_sync(0xffffffffu, ssum, off);
        sx   += __shfl_xor_sync(0xffffffffu, sx,   off);
        sy   += __shfl_xor_sync(0xffffffffu, sy,   off);
        sz   += __shfl_xor_sync(0xffffffffu, sz,   off);
    }

    __shared__ float sh[4][8];
    if (lane == 0) { sh[0][warp] = ssum; sh[1][warp] = sx; sh[2][warp] = sy; sh[3][warp] = sz; }
    __syncthreads();

    __shared__ bool s_last;
    if (threadIdx.x == 0) {
        float t0 = 0.f, t1 = 0.f, t2 = 0.f, t3 = 0.f;
        #pragma unroll
        for (int w = 0; w < 8; w++) {
            t0 += sh[0][w]; t1 += sh[1][w]; t2 += sh[2][w]; t3 += sh[3][w];
        }
        g_part[cta] = make_float4(t0, t1, t2, t3);
        __threadfence();
        const unsigned old = atomicAdd(&g_count, 1u);
        s_last = (old == NCTA - 1);
    }
    __syncthreads();
    if (!s_last) return;

    // ---- finalize in the last CTA ----
    __threadfence();

    const int tid = threadIdx.x;
    double loss = 0.0, tx = 0.0, ty = 0.0, tz = 0.0;
    if (tid < NBC) {
        double crn = 0.0, rt = 0.0;
        #pragma unroll
        for (int k = 0; k < 8; k++) {          // 4 hblocks x 2 zhalves
            const float4 a = g_part[tid * 8 + k];
            if ((k & 1) == 0) crn += (double)a.x;   // zh=0 -> crown (d 0..31)
            else              rt  += (double)a.x;   // zh=1 -> root  (d 32..63)
            tx += (double)a.y; ty += (double)a.z; tz += (double)a.w;
        }
        if ((crn + rt) > 0.0 && rt > 0.0) {
            const double r = crn / rt - 1.2;
            loss = r * r;
        }
    }

    #pragma unroll
    for (int off = 16; off > 0; off >>= 1) {
        loss += __shfl_xor_sync(0xffffffffu, loss, off);
        tx   += __shfl_xor_sync(0xffffffffu, tx,   off);
        ty   += __shfl_xor_sync(0xffffffffu, ty,   off);
        tz   += __shfl_xor_sync(0xffffffffu, tz,   off);
    }

    __shared__ double shd[4][8];
    if (lane == 0) { shd[0][warp] = loss; shd[1][warp] = tx; shd[2][warp] = ty; shd[3][warp] = tz; }
    __syncthreads();

    if (tid == 0) {
        double L = 0.0, Tx = 0.0, Ty = 0.0, Tz = 0.0;
        #pragma unroll
        for (int w = 0; w < 8; w++) {
            L += shd[0][w]; Tx += shd[1][w]; Ty += shd[2][w]; Tz += shd[3][w];
        }
        const double cr_loss = L / (double)NBC;
        const double Nx = (double)BB * CC * DD * HH * (WW - 1);
        const double Ny = (double)BB * CC * DD * (HH - 1) * WW;
        const double Nz = (double)BB * CC * (DD - 1) * HH * WW;
        const double tv = Tx / Nx + Ty / Ny + Tz / Nz;

        const double crown_root = cr_loss * 2.0;   // CROWN_ROOT_W
        const double smooth     = tv * 1.5;        // SMOOTH_W
        out[0] = (float)crown_root;
        out[1] = (float)smooth;
        out[2] = (float)(crown_root + smooth);

        g_count = 0;   // reset for next graph replay
    }
}

extern "C" void kernel_launch(void* const* d_in, const int* in_sizes, int n_in,
                              void* d_out, int out_size) {
    const float* seg = (const float*)d_in[0];
    float* out = (float*)d_out;
    fused_kernel<<<NCTA, 256>>>(seg, out);
}

// round 15
// speedup vs baseline: 1.3319x; 1.0121x over previous
#include <cuda_runtime.h>

#define BB 2
#define CC 32
#define DD 64
#define HH 128
#define WW 128
#define NBC (BB*CC)
#define SLICE (HH*WW)
#define NCTA 512             // 64 bc x 4 hblocks(32 rows) x 2 zhalves

// Per-CTA partials [sum, sx, sy, sz]; fully rewritten each run.
__device__ float4 g_part[NCTA];
__device__ unsigned int g_count;   // zero at load; last CTA resets to 0

// ---- packed f32x2 helpers ----
__device__ __forceinline__ void unpack2(unsigned long long v, float& lo, float& hi) {
    asm("mov.b64 {%0,%1}, %2;" : "=f"(lo), "=f"(hi) : "l"(v));
}
__device__ __forceinline__ void acc2(unsigned long long& acc, unsigned long long v) {
    asm("add.rn.f32x2 %0, %0, %1;" : "+l"(acc) : "l"(v));
}
// acc += |b - a| elementwise (packed)
__device__ __forceinline__ void absdiff_acc2(unsigned long long& acc,
                                             unsigned long long a,
                                             unsigned long long b,
                                             unsigned long long neg1) {
    unsigned long long d;
    asm("fma.rn.f32x2 %0, %1, %2, %3;" : "=l"(d) : "l"(a), "l"(neg1), "l"(b)); // b - a
    asm("and.b64 %0, %0, 0x7FFFFFFF7FFFFFFF;" : "+l"(d));
    asm("add.rn.f32x2 %0, %0, %1;" : "+l"(acc) : "l"(d));
}
__device__ __forceinline__ float hadd2(unsigned long long v) {
    float a, b; unpack2(v, a, b); return a + b;
}

// streaming (evict-first) 16B load with 256B L2 prefetch — single-use bulk stream
__device__ __forceinline__ ulonglong2 ldcs128(const float* base, int roff, int lane) {
    ulonglong2 v;
    const float* p = base + roff + lane * 4;
    asm volatile("ld.global.cs.L2::256B.v2.u64 {%0, %1}, [%2];"
                 : "=l"(v.x), "=l"(v.y) : "l"(p));
    return v;
}
// default-cached 16B load — lines that a neighbor (or this CTA) re-reads
__device__ __forceinline__ ulonglong2 ldca128(const float* base, int roff, int lane) {
    ulonglong2 v;
    const float* p = base + roff + lane * 4;
    asm volatile("ld.global.ca.v2.u64 {%0, %1}, [%2];"
                 : "=l"(v.x), "=l"(v.y) : "l"(p));
    return v;
}
// last-use 16B load — dead after this read
__device__ __forceinline__ ulonglong2 ldlu128(const float* base, int roff, int lane) {
    ulonglong2 v;
    const float* p = base + roff + lane * 4;
    asm volatile("ld.global.lu.v2.u64 {%0, %1}, [%2];"
                 : "=l"(v.x), "=l"(v.y) : "l"(p));
    return v;
}

// x-diffs for one row held as (r.x=x0x1, r.y=x2x3)
__device__ __forceinline__ float xdiff_row(const ulonglong2& r, int lane) {
    float x0, x1, x2, x3;
    unpack2(r.x, x0, x1);
    unpack2(r.y, x2, x3);
    const float nlx = __shfl_down_sync(0xffffffffu, x0, 1);
    float s = fabsf(x1 - x0) + fabsf(x2 - x1) + fabsf(x3 - x2);
    if (lane < 31) s += fabsf(nlx - x3);
    return s;
}

// CTA = (bc, 32-row block, z-half). 8 warps; warp w carries 4 consecutive rows
// h0..h0+3 across 32 z-slices. 3 of 4 y-diffs are register-register; the seam
// y-diff loads row h0+4 — that row is warp w+1's row 0, which warp w+1's
// prefetch fetched with .ca, so it stays L1-resident. z-diff uses the
// prefetched next-slice quad. zh=0 additionally loads slice 32 once for the
// z seam (L2 hit: zh=1's prologue loaded those lines with .ca).
__global__ void __launch_bounds__(256) fused_kernel(const float* __restrict__ seg,
                                                    float* __restrict__ out) {
    const int cta  = blockIdx.x;
    const int bc   = cta >> 3;
    const int rem  = cta & 7;
    const int hb   = rem >> 1;           // 0..3 (32-row blocks)
    const int zh   = rem & 1;
    const int warp = threadIdx.x >> 5;
    const int lane = threadIdx.x & 31;
    const int h0   = hb * 32 + warp * 4;
    const bool has_y = (h0 + 4 < HH);    // false only for rows 124..127
    const unsigned long long neg1 = 0xBF800000BF800000ULL;

    const float* p = seg + (size_t)bc * DD * SLICE + (size_t)(zh * 32) * SLICE + h0 * WW;

    unsigned long long acc_s = 0ULL, acc_y = 0ULL, acc_z = 0ULL;
    float sx = 0.f;

    // Prologue quad: zh=1's first slice (d=32) is re-read by the zh=0 neighbor's
    // z-seam -> keep cacheable (.ca).
    ulonglong2 c[4];
    #pragma unroll
    for (int r = 0; r < 4; r++)
        c[r] = ldca128(p, r * WW, lane);

    #pragma unroll 1
    for (int i = 0; i < 31; i++) {
        // prefetch next-slice quad: row 0 with .ca (it is the previous warp's
        // y-seam line -> keep L1-resident), rows 1-3 streaming.
        ulonglong2 n[4];
        n[0] = ldca128(p, SLICE, lane);
        #pragma unroll
        for (int r = 1; r < 4; r++)
            n[r] = ldcs128(p, SLICE + r * WW, lane);
        ulonglong2 yn;
        if (has_y) yn = ldca128(p, 4 * WW, lane);

        // slice sums + x-diffs
        #pragma unroll
        for (int r = 0; r < 4; r++) {
            acc2(acc_s, c[r].x); acc2(acc_s, c[r].y);
            sx += xdiff_row(c[r], lane);
        }
        // y: 3 in-quad diffs + seam
        #pragma unroll
        for (int r = 0; r < 3; r++) {
            absdiff_acc2(acc_y, c[r].x, c[r + 1].x, neg1);
            absdiff_acc2(acc_y, c[r].y, c[r + 1].y, neg1);
        }
        if (has_y) {
            absdiff_acc2(acc_y, c[3].x, yn.x, neg1);
            absdiff_acc2(acc_y, c[3].y, yn.y, neg1);
        }
        // z: diff vs prefetched next slice
        #pragma unroll
        for (int r = 0; r < 4; r++) {
            absdiff_acc2(acc_z, c[r].x, n[r].x, neg1);
            absdiff_acc2(acc_z, c[r].y, n[r].y, neg1);
            c[r] = n[r];
        }
        p += SLICE;
    }

    // epilogue: local slice 31 (global d = zh*32 + 31)
    {
        ulonglong2 yn;
        if (has_y) yn = ldca128(p, 4 * WW, lane);

        #pragma unroll
        for (int r = 0; r < 4; r++) {
            acc2(acc_s, c[r].x); acc2(acc_s, c[r].y);
            sx += xdiff_row(c[r], lane);
        }
        #pragma unroll
        for (int r = 0; r < 3; r++) {
            absdiff_acc2(acc_y, c[r].x, c[r + 1].x, neg1);
            absdiff_acc2(acc_y, c[r].y, c[r + 1].y, neg1);
        }
        if (has_y) {
            absdiff_acc2(acc_y, c[3].x, yn.x, neg1);
            absdiff_acc2(acc_y, c[3].y, yn.y, neg1);
        }
        if (zh == 0) {   // z seam (slice 31 vs 32) owned by left CTA; dead after use
            #pragma unroll
            for (int r = 0; r < 4; r++) {
                const ulonglong2 n = ldlu128(p, SLICE + r * WW, lane);
                absdiff_acc2(acc_z, c[r].x, n.x, neg1);
                absdiff_acc2(acc_z, c[r].y, n.y, neg1);
            }
        }
    }

    float ssum = hadd2(acc_s);
    float sy   = hadd2(acc_y);
    float sz   = hadd2(acc_z);

    #pragma unroll
    for (int off = 16; off > 0; off >>= 1) {
        ssum += __shfl_xor_sync(0xffffffffu, ssum, off);
        sx   += __shfl_xor_sync(0xffffffffu, sx,   off);
        sy   += __shfl_xor_sync(0xffffffffu, sy,   off);
        sz   += __shfl_xor_sync(0xffffffffu, sz,   off);
    }

    __shared__ float sh[4][8];
    if (lane == 0) { sh[0][warp] = ssum; sh[1][warp] = sx; sh[2][warp] = sy; sh[3][warp] = sz; }
    __syncthreads();

    __shared__ bool s_last;
    if (threadIdx.x == 0) {
        float t0 = 0.f, t1 = 0.f, t2 = 0.f, t3 = 0.f;
        #pragma unroll
        for (int w = 0; w < 8; w++) {
            t0 += sh[0][w]; t1 += sh[1][w]; t2 += sh[2][w]; t3 += sh[3][w];
        }
        g_part[cta] = make_float4(t0, t1, t2, t3);
        __threadfence();
        const unsigned old = atomicAdd(&g_count, 1u);
        s_last = (old == NCTA - 1);
    }
    __syncthreads();
    if (!s_last) return;

    // ---- finalize in the last CTA ----
    __threadfence();

    const int tid = threadIdx.x;
    double loss = 0.0, tx = 0.0, ty = 0.0, tz = 0.0;
    if (tid < NBC) {
        double crn = 0.0, rt = 0.0;
        #pragma unroll
        for (int k = 0; k < 8; k++) {          // 4 hblocks x 2 zhalves
            const float4 a = g_part[tid * 8 + k];
            if ((k & 1) == 0) crn += (double)a.x;   // zh=0 -> crown (d 0..31)
            else              rt  += (double)a.x;   // zh=1 -> root  (d 32..63)
            tx += (double)a.y; ty += (double)a.z; tz += (double)a.w;
        }
        if ((crn + rt) > 0.0 && rt > 0.0) {
            const double r = crn / rt - 1.2;
            loss = r * r;
        }
    }

    #pragma unroll
    for (int off = 16; off > 0; off >>= 1) {
        loss += __shfl_xor_sync(0xffffffffu, loss, off);
        tx   += __shfl_xor_sync(0xffffffffu, tx,   off);
        ty   += __shfl_xor_sync(0xffffffffu, ty,   off);
        tz   += __shfl_xor_sync(0xffffffffu, tz,   off);
    }

    __shared__ double shd[4][8];
    if (lane == 0) { shd[0][warp] = loss; shd[1][warp] = tx; shd[2][warp] = ty; shd[3][warp] = tz; }
    __syncthreads();

    if (tid == 0) {
        double L = 0.0, Tx = 0.0, Ty = 0.0, Tz = 0.0;
        #pragma unroll
        for (int w = 0; w < 8; w++) {
            L += shd[0][w]; Tx += shd[1][w]; Ty += shd[2][w]; Tz += shd[3][w];
        }
        const double cr_loss = L / (double)NBC;
        const double Nx = (double)BB * CC * DD * HH * (WW - 1);
        const double Ny = (double)BB * CC * DD * (HH - 1) * WW;
        const double Nz = (double)BB * CC * (DD - 1) * HH * WW;
        const double tv = Tx / Nx + Ty / Ny + Tz / Nz;

        const double crown_root = cr_loss * 2.0;   // CROWN_ROOT_W
        const double smooth     = tv * 1.5;        // SMOOTH_W
        out[0] = (float)crown_root;
        out[1] = (float)smooth;
        out[2] = (float)(crown_root + smooth);

        g_count = 0;   // reset for next graph replay
    }
}

extern "C" void kernel_launch(void* const* d_in, const int* in_sizes, int n_in,
                              void* d_out, int out_size) {
    const float* seg = (const float*)d_in[0];
    float* out = (float*)d_out;
    fused_kernel<<<NCTA, 256>>>(seg, out);
}

// round 16
// speedup vs baseline: 1.3779x; 1.0346x over previous
#include <cuda_runtime.h>

#define BB 2
#define CC 32
#define DD 64
#define HH 128
#define WW 128
#define NBC (BB*CC)
#define SLICE (HH*WW)
#define NCTA 512             // 64 bc x 4 hblocks(32 rows) x 2 zhalves

// Per-CTA partials [sum, sx, sy, sz]; fully rewritten each run.
__device__ float4 g_part[NCTA];
__device__ unsigned int g_count;   // zero at load; last CTA resets to 0

// ---- packed f32x2 helpers ----
__device__ __forceinline__ void unpack2(unsigned long long v, float& lo, float& hi) {
    asm("mov.b64 {%0,%1}, %2;" : "=f"(lo), "=f"(hi) : "l"(v));
}
__device__ __forceinline__ void acc2(unsigned long long& acc, unsigned long long v) {
    asm("add.rn.f32x2 %0, %0, %1;" : "+l"(acc) : "l"(v));
}
// acc += |b - a| elementwise (packed)
__device__ __forceinline__ void absdiff_acc2(unsigned long long& acc,
                                             unsigned long long a,
                                             unsigned long long b,
                                             unsigned long long neg1) {
    unsigned long long d;
    asm("fma.rn.f32x2 %0, %1, %2, %3;" : "=l"(d) : "l"(a), "l"(neg1), "l"(b)); // b - a
    asm("and.b64 %0, %0, 0x7FFFFFFF7FFFFFFF;" : "+l"(d));
    asm("add.rn.f32x2 %0, %0, %1;" : "+l"(acc) : "l"(d));
}
__device__ __forceinline__ float hadd2(unsigned long long v) {
    float a, b; unpack2(v, a, b); return a + b;
}

// L2 evict-first access policy (single-use bulk stream)
__device__ __forceinline__ unsigned long long mk_stream_policy() {
    unsigned long long p;
    asm("createpolicy.fractional.L2::evict_first.b64 %0, 1.0;" : "=l"(p));
    return p;
}
// streaming 16B load: no L1 allocation, L2 evict-first, 256B L2 prefetch
__device__ __forceinline__ ulonglong2 ldstream128(const float* base, int roff, int lane,
                                                  unsigned long long pol) {
    ulonglong2 v;
    const float* p = base + roff + lane * 4;
    asm volatile("ld.global.L1::no_allocate.L2::cache_hint.L2::256B.v2.u64 "
                 "{%0, %1}, [%2], %3;"
                 : "=l"(v.x), "=l"(v.y) : "l"(p), "l"(pol));
    return v;
}
// default-cached 16B load — lines that a neighbor (or this CTA) re-reads
__device__ __forceinline__ ulonglong2 ldca128(const float* base, int roff, int lane) {
    ulonglong2 v;
    const float* p = base + roff + lane * 4;
    asm volatile("ld.global.ca.v2.u64 {%0, %1}, [%2];"
                 : "=l"(v.x), "=l"(v.y) : "l"(p));
    return v;
}
// last-use 16B load — dead after this read
__device__ __forceinline__ ulonglong2 ldlu128(const float* base, int roff, int lane) {
    ulonglong2 v;
    const float* p = base + roff + lane * 4;
    asm volatile("ld.global.lu.v2.u64 {%0, %1}, [%2];"
                 : "=l"(v.x), "=l"(v.y) : "l"(p));
    return v;
}

// x-diffs for one row held as (r.x=x0x1, r.y=x2x3)
__device__ __forceinline__ float xdiff_row(const ulonglong2& r, int lane) {
    float x0, x1, x2, x3;
    unpack2(r.x, x0, x1);
    unpack2(r.y, x2, x3);
    const float nlx = __shfl_down_sync(0xffffffffu, x0, 1);
    float s = fabsf(x1 - x0) + fabsf(x2 - x1) + fabsf(x3 - x2);
    if (lane < 31) s += fabsf(nlx - x3);
    return s;
}

// CTA = (bc, 32-row block, z-half). 8 warps; warp w carries 4 consecutive rows
// h0..h0+3 across 32 z-slices. 3 of 4 y-diffs are register-register; the seam
// y-diff loads row h0+4 — warp w+1's row 0, fetched .ca so it stays L1-resident
// (streaming rows use L1::no_allocate and cannot displace it). z-diff uses the
// prefetched next-slice quad. zh=0 additionally loads slice 32 once for the
// z seam (L2 hit: zh=1's prologue loaded those lines with .ca).
__global__ void __launch_bounds__(256) fused_kernel(const float* __restrict__ seg,
                                                    float* __restrict__ out) {
    const int cta  = blockIdx.x;
    const int bc   = cta >> 3;
    const int rem  = cta & 7;
    const int hb   = rem >> 1;           // 0..3 (32-row blocks)
    const int zh   = rem & 1;
    const int warp = threadIdx.x >> 5;
    const int lane = threadIdx.x & 31;
    const int h0   = hb * 32 + warp * 4;
    const bool has_y = (h0 + 4 < HH);    // false only for rows 124..127
    const unsigned long long neg1 = 0xBF800000BF800000ULL;
    const unsigned long long pol = mk_stream_policy();

    const float* p = seg + (size_t)bc * DD * SLICE + (size_t)(zh * 32) * SLICE + h0 * WW;

    unsigned long long acc_s = 0ULL, acc_y = 0ULL, acc_z = 0ULL;
    float sx = 0.f;

    // Prologue quad: zh=1's first slice (d=32) is re-read by the zh=0 neighbor's
    // z-seam -> keep cacheable (.ca).
    ulonglong2 c[4];
    #pragma unroll
    for (int r = 0; r < 4; r++)
        c[r] = ldca128(p, r * WW, lane);

    #pragma unroll 1
    for (int i = 0; i < 31; i++) {
        // prefetch next-slice quad: row 0 with .ca (it is the previous warp's
        // y-seam line -> keep L1-resident), rows 1-3 streaming (no L1 alloc,
        // L2 evict-first).
        ulonglong2 n[4];
        n[0] = ldca128(p, SLICE, lane);
        #pragma unroll
        for (int r = 1; r < 4; r++)
            n[r] = ldstream128(p, SLICE + r * WW, lane, pol);
        ulonglong2 yn;
        if (has_y) yn = ldca128(p, 4 * WW, lane);

        // slice sums + x-diffs
        #pragma unroll
        for (int r = 0; r < 4; r++) {
            acc2(acc_s, c[r].x); acc2(acc_s, c[r].y);
            sx += xdiff_row(c[r], lane);
        }
        // y: 3 in-quad diffs + seam
        #pragma unroll
        for (int r = 0; r < 3; r++) {
            absdiff_acc2(acc_y, c[r].x, c[r + 1].x, neg1);
            absdiff_acc2(acc_y, c[r].y, c[r + 1].y, neg1);
        }
        if (has_y) {
            absdiff_acc2(acc_y, c[3].x, yn.x, neg1);
            absdiff_acc2(acc_y, c[3].y, yn.y, neg1);
        }
        // z: diff vs prefetched next slice
        #pragma unroll
        for (int r = 0; r < 4; r++) {
            absdiff_acc2(acc_z, c[r].x, n[r].x, neg1);
            absdiff_acc2(acc_z, c[r].y, n[r].y, neg1);
            c[r] = n[r];
        }
        p += SLICE;
    }

    // epilogue: local slice 31 (global d = zh*32 + 31)
    {
        ulonglong2 yn;
        if (has_y) yn = ldca128(p, 4 * WW, lane);

        #pragma unroll
        for (int r = 0; r < 4; r++) {
            acc2(acc_s, c[r].x); acc2(acc_s, c[r].y);
            sx += xdiff_row(c[r], lane);
        }
        #pragma unroll
        for (int r = 0; r < 3; r++) {
            absdiff_acc2(acc_y, c[r].x, c[r + 1].x, neg1);
            absdiff_acc2(acc_y, c[r].y, c[r + 1].y, neg1);
        }
        if (has_y) {
            absdiff_acc2(acc_y, c[3].x, yn.x, neg1);
            absdiff_acc2(acc_y, c[3].y, yn.y, neg1);
        }
        if (zh == 0) {   // z seam (slice 31 vs 32) owned by left CTA; dead after use
            #pragma unroll
            for (int r = 0; r < 4; r++) {
                const ulonglong2 n = ldlu128(p, SLICE + r * WW, lane);
                absdiff_acc2(acc_z, c[r].x, n.x, neg1);
                absdiff_acc2(acc_z, c[r].y, n.y, neg1);
            }
        }
    }

    float ssum = hadd2(acc_s);
    float sy   = hadd2(acc_y);
    float sz   = hadd2(acc_z);

    #pragma unroll
    for (int off = 16; off > 0; off >>= 1) {
        ssum += __shfl_xor_sync(0xffffffffu, ssum, off);
        sx   += __shfl_xor_sync(0xffffffffu, sx,   off);
        sy   += __shfl_xor_sync(0xffffffffu, sy,   off);
        sz   += __shfl_xor_sync(0xffffffffu, sz,   off);
    }

    __shared__ float sh[4][8];
    if (lane == 0) { sh[0][warp] = ssum; sh[1][warp] = sx; sh[2][warp] = sy; sh[3][warp] = sz; }
    __syncthreads();

    __shared__ bool s_last;
    if (threadIdx.x == 0) {
        float t0 = 0.f, t1 = 0.f, t2 = 0.f, t3 = 0.f;
        #pragma unroll
        for (int w = 0; w < 8; w++) {
            t0 += sh[0][w]; t1 += sh[1][w]; t2 += sh[2][w]; t3 += sh[3][w];
        }
        g_part[cta] = make_float4(t0, t1, t2, t3);
        __threadfence();
        const unsigned old = atomicAdd(&g_count, 1u);
        s_last = (old == NCTA - 1);
    }
    __syncthreads();
    if (!s_last) return;

    // ---- finalize in the last CTA ----
    __threadfence();

    const int tid = threadIdx.x;
    double loss = 0.0, tx = 0.0, ty = 0.0, tz = 0.0;
    if (tid < NBC) {
        double crn = 0.0, rt = 0.0;
        #pragma unroll
        for (int k = 0; k < 8; k++) {          // 4 hblocks x 2 zhalves
            const float4 a = g_part[tid * 8 + k];
            if ((k & 1) == 0) crn += (double)a.x;   // zh=0 -> crown (d 0..31)
            else              rt  += (double)a.x;   // zh=1 -> root  (d 32..63)
            tx += (double)a.y; ty += (double)a.z; tz += (double)a.w;
        }
        if ((crn + rt) > 0.0 && rt > 0.0) {
            const double r = crn / rt - 1.2;
            loss = r * r;
        }
    }

    #pragma unroll
    for (int off = 16; off > 0; off >>= 1) {
        loss += __shfl_xor_sync(0xffffffffu, loss, off);
        tx   += __shfl_xor_sync(0xffffffffu, tx,   off);
        ty   += __shfl_xor_sync(0xffffffffu, ty,   off);
        tz   += __shfl_xor_sync(0xffffffffu, tz,   off);
    }

    __shared__ double shd[4][8];
    if (lane == 0) { shd[0][warp] = loss; shd[1][warp] = tx; shd[2][warp] = ty; shd[3][warp] = tz; }
    __syncthreads();

    if (tid == 0) {
        double L = 0.0, Tx = 0.0, Ty = 0.0, Tz = 0.0;
        #pragma unroll
        for (int w = 0; w < 8; w++) {
            L += shd[0][w]; Tx += shd[1][w]; Ty += shd[2][w]; Tz += shd[3][w];
        }
        const double cr_loss = L / (double)NBC;
        const double Nx = (double)BB * CC * DD * HH * (WW - 1);
        const double Ny = (double)BB * CC * DD * (HH - 1) * WW;
        const double Nz = (double)BB * CC * (DD - 1) * HH * WW;
        const double tv = Tx / Nx + Ty / Ny + Tz / Nz;

        const double crown_root = cr_loss * 2.0;   // CROWN_ROOT_W
        const double smooth     = tv * 1.5;        // SMOOTH_W
        out[0] = (float)crown_root;
        out[1] = (float)smooth;
        out[2] = (float)(crown_root + smooth);

        g_count = 0;   // reset for next graph replay
    }
}

extern "C" void kernel_launch(void* const* d_in, const int* in_sizes, int n_in,
                              void* d_out, int out_size) {
    const float* seg = (const float*)d_in[0];
    float* out = (float*)d_out;
    fused_kernel<<<NCTA, 256>>>(seg, out);
}